// round 1
// baseline (speedup 1.0000x reference)
#include <cuda_runtime.h>

// Problem constants
#define Bn  64
#define An  5
#define Cn  80
#define Hn  52
#define Wn  52
#define Tn  32
#define HWn (Hn * Wn)

__device__ __forceinline__ float softplusf(float x) {
    // matches jax.nn.softplus: max(x,0) + log1p(exp(-|x|))
    return fmaxf(x, 0.f) + log1pf(expf(-fabsf(x)));
}

__global__ void init_out_kernel(float* __restrict__ out) {
    if (threadIdx.x < 5) out[threadIdx.x] = 0.f;
}

// One thread per (b, a, h, w): neg-mask (IoU vs last target < 0.6) contribution
// of 0.5/B * softplus(pred_response). Pos positions are corrected (subtracted)
// in tgt_kernel — target positions are unique per batch by construction.
__global__ void neg_kernel(const float* __restrict__ pred_response,
                           const float* __restrict__ pred_bboxes,
                           const float* __restrict__ tgt_box,
                           const int*   __restrict__ tix,
                           const int*   __restrict__ tiy,
                           float* __restrict__ out)
{
    int idx = blockIdx.x * blockDim.x + threadIdx.x;
    float acc = 0.f;
    if (idx < Bn * An * HWn) {
        int w  = idx % Wn;
        int h  = (idx / Wn) % Hn;
        int ba = idx / HWn;          // b*A + a
        int b  = ba / An;

        const float* pb = pred_bboxes + (size_t)ba * 4 * HWn + h * Wn + w;
        float p0 = pb[0];
        float p1 = pb[HWn];
        float pw = pb[2 * HWn];
        float ph = pb[3 * HWn];

        float px1 = 1.f / (1.f + expf(-p0)) + (float)w - pw * 0.5f;
        float py1 = 1.f / (1.f + expf(-p1)) + (float)h - ph * 0.5f;

        // last target (t = T-1) of batch b
        const float* tb = tgt_box + ((size_t)b * Tn + (Tn - 1)) * 4;
        float tw  = tb[2], th = tb[3];
        float gx1 = tb[0] + (float)tix[b * Tn + Tn - 1] - tw * 0.5f;
        float gy1 = tb[1] + (float)tiy[b * Tn + Tn - 1] - th * 0.5f;

        float dx    = fmaxf(fminf(px1 + pw, gx1 + tw) - fmaxf(px1, gx1), 0.f);
        float dy    = fmaxf(fminf(py1 + ph, gy1 + th) - fmaxf(py1, gy1), 0.f);
        float inter = dx * dy;
        float iou   = inter / (pw * ph + tw * th - inter);

        if (iou < 0.6f) {
            acc = softplusf(pred_response[(size_t)ba * HWn + h * Wn + w]);
        }
    }

    // block reduce (256 threads = 8 warps)
    #pragma unroll
    for (int o = 16; o; o >>= 1) acc += __shfl_xor_sync(0xffffffffu, acc, o);
    __shared__ float sm[8];
    int lane = threadIdx.x & 31;
    int wrp  = threadIdx.x >> 5;
    if (lane == 0) sm[wrp] = acc;
    __syncthreads();
    if (wrp == 0) {
        float v = (lane < 8) ? sm[lane] : 0.f;
        #pragma unroll
        for (int o = 4; o; o >>= 1) v += __shfl_xor_sync(0xffffffffu, v, o);
        if (lane == 0) atomicAdd(&out[1], v * (0.5f / Bn));   // L_NOOBJ / B
    }
}

// One warp per (b, t) target: class CE (warp-parallel over 80 logits),
// pos-response loss, neg-mask correction, xy BCE, wh L2.
__global__ void tgt_kernel(const float* __restrict__ pred_cls,
                           const float* __restrict__ pred_response,
                           const float* __restrict__ pred_bboxes,
                           const float* __restrict__ tgt_box,
                           const int*   __restrict__ tix,
                           const int*   __restrict__ tiy,
                           const int*   __restrict__ tib,
                           const int*   __restrict__ tlab,
                           float* __restrict__ out)
{
    int gwid = (blockIdx.x * blockDim.x + threadIdx.x) >> 5;  // 0..B*T-1 (exact)
    int lane = threadIdx.x & 31;
    int b  = gwid / Tn;
    int bt = gwid;                 // b*T + t

    int x   = tix[bt];
    int y   = tiy[bt];
    int a   = tib[bt];
    int lab = tlab[bt];

    const float* tb = tgt_box + (size_t)bt * 4;
    float tx = tb[0], ty = tb[1], tw = tb[2], th = tb[3];

    int sp = y * Wn + x;
    int ba = b * An + a;
    const float* pbp = pred_bboxes + (size_t)ba * 4 * HWn + sp;
    float p0 = pbp[0], p1 = pbp[HWn], pw = pbp[2 * HWn], ph = pbp[3 * HWn];

    // ---- class cross-entropy (warp-collective over C=80) ----
    const float* pc = pred_cls + (size_t)ba * Cn * HWn + sp;
    float lv0 = pc[(size_t)lane * HWn];                                  // lanes 0..31
    float lv1 = pc[(size_t)(lane + 32) * HWn];                           // 32..63
    float lv2 = (lane + 64 < Cn) ? pc[(size_t)(lane + 64) * HWn] : -INFINITY; // 64..79

    float m = fmaxf(lv0, fmaxf(lv1, lv2));
    #pragma unroll
    for (int o = 16; o; o >>= 1) m = fmaxf(m, __shfl_xor_sync(0xffffffffu, m, o));

    float s = expf(lv0 - m) + expf(lv1 - m);
    float ll = 0.f;
    if (lane == lab)        ll = lv0;
    if (lane + 32 == lab)   ll = lv1;
    if (lane + 64 < Cn) {
        s += expf(lv2 - m);
        if (lane + 64 == lab) ll = lv2;
    }
    #pragma unroll
    for (int o = 16; o; o >>= 1) {
        s  += __shfl_xor_sync(0xffffffffu, s, o);
        ll += __shfl_xor_sync(0xffffffffu, ll, o);
    }
    float loss_cls = m + logf(s) - ll;   // lse - logit[label]

    // ---- scalar per-target terms (lane 0) ----
    float loss_pos = 0.f, neg_sub = 0.f, loss_xy = 0.f, loss_wh = 0.f;
    if (lane == 0) {
        float px1 = 1.f / (1.f + expf(-p0)) + (float)x - pw * 0.5f;
        float py1 = 1.f / (1.f + expf(-p1)) + (float)y - ph * 0.5f;

        // IoU with own target (cx = tx + x, cy = ty + y)
        float gx1 = tx + (float)x - tw * 0.5f;
        float gy1 = ty + (float)y - th * 0.5f;
        float dx    = fmaxf(fminf(px1 + pw, gx1 + tw) - fmaxf(px1, gx1), 0.f);
        float dy    = fmaxf(fminf(py1 + ph, gy1 + th) - fmaxf(py1, gy1), 0.f);
        float inter = dx * dy;
        float iou_sel = inter / (pw * ph + tw * th - inter);

        float pr = pred_response[(size_t)ba * HWn + sp];
        loss_pos = softplusf(pr) - pr * iou_sel;        // bce(pr, iou_sel)

        // neg-mask correction: was this pos position counted as neg in neg_kernel?
        const float* tb2 = tgt_box + ((size_t)b * Tn + Tn - 1) * 4;
        float tw2  = tb2[2], th2 = tb2[3];
        float g2x1 = tb2[0] + (float)tix[b * Tn + Tn - 1] - tw2 * 0.5f;
        float g2y1 = tb2[1] + (float)tiy[b * Tn + Tn - 1] - th2 * 0.5f;
        float dx2    = fmaxf(fminf(px1 + pw, g2x1 + tw2) - fmaxf(px1, g2x1), 0.f);
        float dy2    = fmaxf(fminf(py1 + ph, g2y1 + th2) - fmaxf(py1, g2y1), 0.f);
        float inter2 = dx2 * dy2;
        float iou2   = inter2 / (pw * ph + tw2 * th2 - inter2);
        if (iou2 < 0.6f) neg_sub = softplusf(pr);

        loss_xy = (softplusf(p0) - p0 * tx) + (softplusf(p1) - p1 * ty);
        loss_wh = (pw - tw) * (pw - tw) + (ph - th) * (ph - th);
    }

    // ---- block reduce 5 partials across 8 warps, then atomics ----
    __shared__ float sm[8][5];
    int wrp = threadIdx.x >> 5;
    if (lane == 0) {
        sm[wrp][0] = loss_pos;
        sm[wrp][1] = -neg_sub;     // subtract from loss_neg
        sm[wrp][2] = loss_cls;
        sm[wrp][3] = loss_xy;
        sm[wrp][4] = loss_wh;
    }
    __syncthreads();
    if (threadIdx.x < 5) {
        float v = 0.f;
        #pragma unroll
        for (int i = 0; i < 8; i++) v += sm[i][threadIdx.x];
        float scale;
        switch (threadIdx.x) {
            case 0: scale = 1.0f / Bn; break;   // L_OBJ / B
            case 1: scale = 0.5f / Bn; break;   // L_NOOBJ / B
            case 2: scale = 1.0f / Bn; break;
            case 3: scale = 1.0f / Bn; break;
            default: scale = 5.0f / Bn; break;  // L_COORD / B
        }
        atomicAdd(&out[threadIdx.x], v * scale);
    }
}

extern "C" void kernel_launch(void* const* d_in, const int* in_sizes, int n_in,
                              void* d_out, int out_size)
{
    const float* pred_cls      = (const float*)d_in[0];
    const float* pred_response = (const float*)d_in[1];
    const float* pred_bboxes   = (const float*)d_in[2];
    const float* tgt_box       = (const float*)d_in[3];
    const int*   tgt_idx_x     = (const int*)d_in[4];
    const int*   tgt_idx_y     = (const int*)d_in[5];
    const int*   tgt_idx_box   = (const int*)d_in[6];
    const int*   tgt_label     = (const int*)d_in[7];
    float* out = (float*)d_out;

    init_out_kernel<<<1, 32>>>(out);

    const int total = Bn * An * HWn;               // 865280
    neg_kernel<<<(total + 255) / 256, 256>>>(pred_response, pred_bboxes,
                                             tgt_box, tgt_idx_x, tgt_idx_y, out);

    // B*T = 2048 targets, one warp each: 256 blocks x 256 threads (8 warps)
    tgt_kernel<<<(Bn * Tn) / 8, 256>>>(pred_cls, pred_response, pred_bboxes,
                                       tgt_box, tgt_idx_x, tgt_idx_y,
                                       tgt_idx_box, tgt_label, out);
}

// round 3
// speedup vs baseline: 1.1711x; 1.1711x over previous
#include <cuda_runtime.h>

// Problem constants
#define Bn  64
#define An  5
#define Cn  80
#define Hn  52
#define Wn  52
#define Tn  32
#define HWn (Hn * Wn)          // 2704
#define QWn (HWn / 4)          // 676 float4s per plane

#define NEG_BLOCKS 845          // 216320 vec4-elems / 256
#define TGT_BLOCKS 256          // 2048 warps / 8
#define GRID (NEG_BLOCKS + TGT_BLOCKS)

// Persistent scratch (zero at module load; final block resets after each run)
__device__ float        g_scratch[5];
__device__ unsigned int g_count;

__device__ __forceinline__ float softplusf(float x) {
    return fmaxf(x, 0.f) + log1pf(__expf(-fabsf(x)));
}
__device__ __forceinline__ float sigmoidf_(float x) {
    return 1.f / (1.f + __expf(-x));
}

__device__ __forceinline__ void finalize(float* v5, int nvals, float* __restrict__ out) {
    // v5: this thread's partial for index threadIdx.x (<nvals), already scaled.
    // warp-reduced partials must already be accumulated; here we get per-block
    // sums in sm and do the atomics + ticket.
    __shared__ bool is_last;
    if (threadIdx.x < nvals) atomicAdd(&g_scratch[threadIdx.x], v5[0]);
    __threadfence();
    if (threadIdx.x == 0) {
        unsigned prev = atomicAdd(&g_count, 1u);
        is_last = (prev == GRID - 1);
    }
    __syncthreads();
    if (is_last) {
        __threadfence();
        if (threadIdx.x < 5) {
            volatile float* vs = g_scratch;
            out[threadIdx.x] = vs[threadIdx.x];
            g_scratch[threadIdx.x] = 0.f;
        }
        if (threadIdx.x == 0) g_count = 0u;
    }
}

__global__ void __launch_bounds__(256)
fused_kernel(const float* __restrict__ pred_cls,
             const float* __restrict__ pred_response,
             const float* __restrict__ pred_bboxes,
             const float* __restrict__ tgt_box,
             const int*   __restrict__ tix,
             const int*   __restrict__ tiy,
             const int*   __restrict__ tib,
             const int*   __restrict__ tlab,
             float* __restrict__ out)
{
    int lane = threadIdx.x & 31;
    int wrp  = threadIdx.x >> 5;
    __shared__ float sm[8][5];

    if (blockIdx.x < NEG_BLOCKS) {
        // ---------------- negative-response pass (float4) ----------------
        int t  = blockIdx.x * 256 + threadIdx.x;      // 0..216319 exact
        int ba = t / QWn;                              // b*A + a
        int p  = (t - ba * QWn) * 4;                   // pixel base (row-aligned)
        int b  = ba / An;
        int h  = p / Wn;
        int w  = p - h * Wn;

        const float4* pb = (const float4*)(pred_bboxes + (size_t)ba * 4 * HWn + p);
        float4 v0 = pb[0];
        float4 v1 = pb[QWn];           // float4 stride = HWn/4
        float4 vw = pb[2 * QWn];
        float4 vh = pb[3 * QWn];
        float4 pr = ((const float4*)(pred_response + (size_t)ba * HWn + p))[0];

        // last target of batch b
        const float* tb = tgt_box + ((size_t)b * Tn + (Tn - 1)) * 4;
        float tw  = tb[2], th = tb[3];
        float gx1 = tb[0] + (float)tix[b * Tn + Tn - 1] - tw * 0.5f;
        float gy1 = tb[1] + (float)tiy[b * Tn + Tn - 1] - th * 0.5f;
        float gx2 = gx1 + tw, gy2 = gy1 + th;
        float tarea = tw * th;

        float acc = 0.f;
        float P0[4] = {v0.x, v0.y, v0.z, v0.w};
        float P1[4] = {v1.x, v1.y, v1.z, v1.w};
        float PW[4] = {vw.x, vw.y, vw.z, vw.w};
        float PH[4] = {vh.x, vh.y, vh.z, vh.w};
        float PR[4] = {pr.x, pr.y, pr.z, pr.w};
        #pragma unroll
        for (int j = 0; j < 4; j++) {
            float pw_ = PW[j], ph_ = PH[j];
            float px1 = sigmoidf_(P0[j]) + (float)(w + j) - pw_ * 0.5f;
            float py1 = sigmoidf_(P1[j]) + (float)h       - ph_ * 0.5f;
            float dx    = fmaxf(fminf(px1 + pw_, gx2) - fmaxf(px1, gx1), 0.f);
            float dy    = fmaxf(fminf(py1 + ph_, gy2) - fmaxf(py1, gy1), 0.f);
            float inter = dx * dy;
            float iou   = inter / (pw_ * ph_ + tarea - inter);
            if (iou < 0.6f) acc += softplusf(PR[j]);
        }

        #pragma unroll
        for (int o = 16; o; o >>= 1) acc += __shfl_xor_sync(0xffffffffu, acc, o);
        if (lane == 0) sm[wrp][0] = acc;
        __syncthreads();
        float v = 0.f;
        if (threadIdx.x == 1) {     // index 1 = loss_neg
            #pragma unroll
            for (int i = 0; i < 8; i++) v += sm[i][0];
            v *= (0.5f / Bn);
        }
        finalize(&v, 5, out);
    } else {
        // ---------------- per-target pass (1 warp per target) ----------------
        int gw = (blockIdx.x - NEG_BLOCKS) * 8 + wrp;  // 0..2047
        int bt = gw;
        int b  = gw / Tn;

        int x   = tix[bt];
        int y   = tiy[bt];
        int a   = tib[bt];
        int lab = tlab[bt];

        const float* tb = tgt_box + (size_t)bt * 4;
        float tx = tb[0], ty = tb[1], tw = tb[2], th = tb[3];

        int sp = y * Wn + x;
        int ba = b * An + a;
        const float* pbp = pred_bboxes + (size_t)ba * 4 * HWn + sp;
        float p0 = pbp[0], p1 = pbp[HWn], pw_ = pbp[2 * HWn], ph_ = pbp[3 * HWn];

        // ---- class CE (warp-collective over C=80) ----
        const float* pc = pred_cls + (size_t)ba * Cn * HWn + sp;
        float lv0 = pc[(size_t)lane * HWn];
        float lv1 = pc[(size_t)(lane + 32) * HWn];
        float lv2 = (lane + 64 < Cn) ? pc[(size_t)(lane + 64) * HWn] : -INFINITY;

        float m = fmaxf(lv0, fmaxf(lv1, lv2));
        #pragma unroll
        for (int o = 16; o; o >>= 1) m = fmaxf(m, __shfl_xor_sync(0xffffffffu, m, o));

        float s = __expf(lv0 - m) + __expf(lv1 - m);
        float ll = 0.f;
        if (lane == lab)      ll = lv0;
        if (lane + 32 == lab) ll = lv1;
        if (lane + 64 < Cn) {
            s += __expf(lv2 - m);
            if (lane + 64 == lab) ll = lv2;
        }
        #pragma unroll
        for (int o = 16; o; o >>= 1) {
            s  += __shfl_xor_sync(0xffffffffu, s, o);
            ll += __shfl_xor_sync(0xffffffffu, ll, o);
        }
        float loss_cls = m + __logf(s) - ll;

        float loss_pos = 0.f, neg_sub = 0.f, loss_xy = 0.f, loss_wh = 0.f;
        if (lane == 0) {
            float px1 = sigmoidf_(p0) + (float)x - pw_ * 0.5f;
            float py1 = sigmoidf_(p1) + (float)y - ph_ * 0.5f;

            float gx1 = tx + (float)x - tw * 0.5f;
            float gy1 = ty + (float)y - th * 0.5f;
            float dx    = fmaxf(fminf(px1 + pw_, gx1 + tw) - fmaxf(px1, gx1), 0.f);
            float dy    = fmaxf(fminf(py1 + ph_, gy1 + th) - fmaxf(py1, gy1), 0.f);
            float inter = dx * dy;
            float iou_sel = inter / (pw_ * ph_ + tw * th - inter);

            float prr = pred_response[(size_t)ba * HWn + sp];
            loss_pos = softplusf(prr) - prr * iou_sel;

            // neg-mask correction at this (unique) pos position
            const float* tb2 = tgt_box + ((size_t)b * Tn + Tn - 1) * 4;
            float tw2  = tb2[2], th2 = tb2[3];
            float g2x1 = tb2[0] + (float)tix[b * Tn + Tn - 1] - tw2 * 0.5f;
            float g2y1 = tb2[1] + (float)tiy[b * Tn + Tn - 1] - th2 * 0.5f;
            float dx2    = fmaxf(fminf(px1 + pw_, g2x1 + tw2) - fmaxf(px1, g2x1), 0.f);
            float dy2    = fmaxf(fminf(py1 + ph_, g2y1 + th2) - fmaxf(py1, g2y1), 0.f);
            float inter2 = dx2 * dy2;
            float iou2   = inter2 / (pw_ * ph_ + tw2 * th2 - inter2);
            if (iou2 < 0.6f) neg_sub = softplusf(prr);

            loss_xy = (softplusf(p0) - p0 * tx) + (softplusf(p1) - p1 * ty);
            loss_wh = (pw_ - tw) * (pw_ - tw) + (ph_ - th) * (ph_ - th);
        }

        if (lane == 0) {
            sm[wrp][0] = loss_pos;
            sm[wrp][1] = -neg_sub;
            sm[wrp][2] = loss_cls;
            sm[wrp][3] = loss_xy;
            sm[wrp][4] = loss_wh;
        }
        __syncthreads();
        float v = 0.f;
        if (threadIdx.x < 5) {
            #pragma unroll
            for (int i = 0; i < 8; i++) v += sm[i][threadIdx.x];
            const float scales[5] = {1.0f / Bn, 0.5f / Bn, 1.0f / Bn, 1.0f / Bn, 5.0f / Bn};
            v *= scales[threadIdx.x];
        }
        finalize(&v, 5, out);
    }
}

extern "C" void kernel_launch(void* const* d_in, const int* in_sizes, int n_in,
                              void* d_out, int out_size)
{
    const float* pred_cls      = (const float*)d_in[0];
    const float* pred_response = (const float*)d_in[1];
    const float* pred_bboxes   = (const float*)d_in[2];
    const float* tgt_box       = (const float*)d_in[3];
    const int*   tgt_idx_x     = (const int*)d_in[4];
    const int*   tgt_idx_y     = (const int*)d_in[5];
    const int*   tgt_idx_box   = (const int*)d_in[6];
    const int*   tgt_label     = (const int*)d_in[7];
    float* out = (float*)d_out;

    fused_kernel<<<GRID, 256>>>(pred_cls, pred_response, pred_bboxes,
                                tgt_box, tgt_idx_x, tgt_idx_y,
                                tgt_idx_box, tgt_label, out);
}

// round 4
// speedup vs baseline: 1.5638x; 1.3353x over previous
#include <cuda_runtime.h>

// Problem constants
#define Bn  64
#define An  5
#define Cn  80
#define Hn  52
#define Wn  52
#define Tn  32
#define HWn (Hn * Wn)          // 2704
#define QWn (HWn / 4)          // 676 float4s per plane

#define NEG_BLOCKS 845          // 216320 vec4-elems / 256
#define TGT_BLOCKS 256          // 2048 warps / 8
#define GRID (NEG_BLOCKS + TGT_BLOCKS)

// Persistent scratch (zero at module load; final block resets after each run)
__device__ float        g_scratch[5];
__device__ unsigned int g_count;

__device__ __forceinline__ float softplusf_(float x) {
    // max(x,0) + log(1 + exp(-|x|));  EX2 + LG2, abs err ~1e-7
    return fmaxf(x, 0.f) + __logf(1.f + __expf(-fabsf(x)));
}
__device__ __forceinline__ float fsigmoid(float x) {
    // sigmoid(x) = 0.5 + 0.5*tanh(x/2) — HW MUFU.TANH, abs err ~1e-5
    float t;
    asm("tanh.approx.f32 %0, %1;" : "=f"(t) : "f"(x * 0.5f));
    return fmaf(t, 0.5f, 0.5f);
}

__device__ __forceinline__ void ticket_and_finalize(float* __restrict__ out) {
    __shared__ bool is_last;
    __threadfence();
    if (threadIdx.x == 0) {
        unsigned prev = atomicAdd(&g_count, 1u);
        is_last = (prev == GRID - 1);
    }
    __syncthreads();
    if (is_last) {
        __threadfence();
        if (threadIdx.x < 5) {
            volatile float* vs = g_scratch;
            out[threadIdx.x] = vs[threadIdx.x];
            g_scratch[threadIdx.x] = 0.f;
        }
        if (threadIdx.x == 0) g_count = 0u;
    }
}

__global__ void __launch_bounds__(256)
fused_kernel(const float* __restrict__ pred_cls,
             const float* __restrict__ pred_response,
             const float* __restrict__ pred_bboxes,
             const float* __restrict__ tgt_box,
             const int*   __restrict__ tix,
             const int*   __restrict__ tiy,
             const int*   __restrict__ tib,
             const int*   __restrict__ tlab,
             float* __restrict__ out)
{
    int lane = threadIdx.x & 31;
    int wrp  = threadIdx.x >> 5;
    __shared__ float sm[8][5];

    if (blockIdx.x < NEG_BLOCKS) {
        // ---------------- negative-response pass (float4, sigmoid-free fast path) ----------------
        int t  = blockIdx.x * 256 + threadIdx.x;      // 0..216319 exact
        int ba = t / QWn;                              // b*A + a
        int p  = (t - ba * QWn) * 4;                   // pixel base (row-aligned)
        int b  = ba / An;
        int h  = p / Wn;
        int w  = p - h * Wn;

        const float4* pb = (const float4*)(pred_bboxes + (size_t)ba * 4 * HWn + p);
        float4 v0 = pb[0];
        float4 v1 = pb[QWn];
        float4 vw = pb[2 * QWn];
        float4 vh = pb[3 * QWn];
        float4 pr = ((const float4*)(pred_response + (size_t)ba * HWn + p))[0];

        // last target of batch b
        const float* tb = tgt_box + ((size_t)b * Tn + (Tn - 1)) * 4;
        float tw  = tb[2], th = tb[3];
        float gx1 = tb[0] + (float)tix[b * Tn + Tn - 1] - tw * 0.5f;
        float gy1 = tb[1] + (float)tiy[b * Tn + Tn - 1] - th * 0.5f;
        float gx2 = gx1 + tw, gy2 = gy1 + th;
        float tarea = tw * th;

        float P0[4] = {v0.x, v0.y, v0.z, v0.w};
        float P1[4] = {v1.x, v1.y, v1.z, v1.w};
        float PW[4] = {vw.x, vw.y, vw.z, vw.w};
        float PH[4] = {vh.x, vh.y, vh.z, vh.w};
        float PR[4] = {pr.x, pr.y, pr.z, pr.w};

        float fh = (float)h;
        float acc = 0.f;
        #pragma unroll
        for (int j = 0; j < 4; j++) {
            float pw_ = PW[j], ph_ = PH[j];
            float hpw = pw_ * 0.5f, hph = ph_ * 0.5f;
            float pwph = pw_ * ph_;
            float fw = (float)(w + j);

            // Interval bound over sigmoid in (0,1): exact implication iou < 0.6
            float dxu = fminf(fw + 1.f + hpw, gx2) - fmaxf(fw - hpw, gx1);
            float dyu = fminf(fh + 1.f + hph, gy2) - fmaxf(fh - hph, gy1);
            float iu  = fmaxf(dxu, 0.f) * fmaxf(dyu, 0.f);

            bool neg;
            if (iu < 0.6f * (pwph + tarea - iu)) {
                neg = true;                            // provably iou < 0.6
            } else {
                float px1 = fsigmoid(P0[j]) + fw - hpw;
                float py1 = fsigmoid(P1[j]) + fh - hph;
                float dx    = fmaxf(fminf(px1 + pw_, gx2) - fmaxf(px1, gx1), 0.f);
                float dy    = fmaxf(fminf(py1 + ph_, gy2) - fmaxf(py1, gy1), 0.f);
                float inter = dx * dy;
                float iou   = inter / (pwph + tarea - inter);
                neg = (iou < 0.6f);
            }
            if (neg) acc += softplusf_(PR[j]);
        }

        #pragma unroll
        for (int o = 16; o; o >>= 1) acc += __shfl_xor_sync(0xffffffffu, acc, o);
        if (lane == 0) sm[wrp][0] = acc;
        __syncthreads();
        if (threadIdx.x == 0) {
            float v = 0.f;
            #pragma unroll
            for (int i = 0; i < 8; i++) v += sm[i][0];
            atomicAdd(&g_scratch[1], v * (0.5f / Bn));   // L_NOOBJ / B
        }
        ticket_and_finalize(out);
    } else {
        // ---------------- per-target pass (1 warp per target) ----------------
        int gw = (blockIdx.x - NEG_BLOCKS) * 8 + wrp;  // 0..2047
        int bt = gw;
        int b  = gw / Tn;

        int x   = tix[bt];
        int y   = tiy[bt];
        int a   = tib[bt];
        int lab = tlab[bt];

        const float* tb = tgt_box + (size_t)bt * 4;
        float tx = tb[0], ty = tb[1], tw = tb[2], th = tb[3];

        int sp = y * Wn + x;
        int ba = b * An + a;
        const float* pbp = pred_bboxes + (size_t)ba * 4 * HWn + sp;
        float p0 = pbp[0], p1 = pbp[HWn], pw_ = pbp[2 * HWn], ph_ = pbp[3 * HWn];

        // ---- class CE (warp-collective over C=80) ----
        const float* pc = pred_cls + (size_t)ba * Cn * HWn + sp;
        float lv0 = pc[(size_t)lane * HWn];
        float lv1 = pc[(size_t)(lane + 32) * HWn];
        float lv2 = (lane + 64 < Cn) ? pc[(size_t)(lane + 64) * HWn] : -INFINITY;

        float m = fmaxf(lv0, fmaxf(lv1, lv2));
        #pragma unroll
        for (int o = 16; o; o >>= 1) m = fmaxf(m, __shfl_xor_sync(0xffffffffu, m, o));

        float s = __expf(lv0 - m) + __expf(lv1 - m);
        float ll = 0.f;
        if (lane == lab)      ll = lv0;
        if (lane + 32 == lab) ll = lv1;
        if (lane + 64 < Cn) {
            s += __expf(lv2 - m);
            if (lane + 64 == lab) ll = lv2;
        }
        #pragma unroll
        for (int o = 16; o; o >>= 1) {
            s  += __shfl_xor_sync(0xffffffffu, s, o);
            ll += __shfl_xor_sync(0xffffffffu, ll, o);
        }
        float loss_cls = m + __logf(s) - ll;

        float loss_pos = 0.f, neg_sub = 0.f, loss_xy = 0.f, loss_wh = 0.f;
        if (lane == 0) {
            float px1 = fsigmoid(p0) + (float)x - pw_ * 0.5f;
            float py1 = fsigmoid(p1) + (float)y - ph_ * 0.5f;

            float gx1 = tx + (float)x - tw * 0.5f;
            float gy1 = ty + (float)y - th * 0.5f;
            float dx    = fmaxf(fminf(px1 + pw_, gx1 + tw) - fmaxf(px1, gx1), 0.f);
            float dy    = fmaxf(fminf(py1 + ph_, gy1 + th) - fmaxf(py1, gy1), 0.f);
            float inter = dx * dy;
            float iou_sel = inter / (pw_ * ph_ + tw * th - inter);

            float prr = pred_response[(size_t)ba * HWn + sp];
            loss_pos = softplusf_(prr) - prr * iou_sel;

            // neg-mask correction at this (unique) pos position
            const float* tb2 = tgt_box + ((size_t)b * Tn + Tn - 1) * 4;
            float tw2  = tb2[2], th2 = tb2[3];
            float g2x1 = tb2[0] + (float)tix[b * Tn + Tn - 1] - tw2 * 0.5f;
            float g2y1 = tb2[1] + (float)tiy[b * Tn + Tn - 1] - th2 * 0.5f;
            float dx2    = fmaxf(fminf(px1 + pw_, g2x1 + tw2) - fmaxf(px1, g2x1), 0.f);
            float dy2    = fmaxf(fminf(py1 + ph_, g2y1 + th2) - fmaxf(py1, g2y1), 0.f);
            float inter2 = dx2 * dy2;
            float iou2   = inter2 / (pw_ * ph_ + tw2 * th2 - inter2);
            if (iou2 < 0.6f) neg_sub = softplusf_(prr);

            loss_xy = (softplusf_(p0) - p0 * tx) + (softplusf_(p1) - p1 * ty);
            loss_wh = (pw_ - tw) * (pw_ - tw) + (ph_ - th) * (ph_ - th);
        }

        if (lane == 0) {
            sm[wrp][0] = loss_pos;
            sm[wrp][1] = -neg_sub;
            sm[wrp][2] = loss_cls;
            sm[wrp][3] = loss_xy;
            sm[wrp][4] = loss_wh;
        }
        __syncthreads();
        if (threadIdx.x < 5) {
            float v = 0.f;
            #pragma unroll
            for (int i = 0; i < 8; i++) v += sm[i][threadIdx.x];
            const float scales[5] = {1.0f / Bn, 0.5f / Bn, 1.0f / Bn, 1.0f / Bn, 5.0f / Bn};
            atomicAdd(&g_scratch[threadIdx.x], v * scales[threadIdx.x]);
        }
        ticket_and_finalize(out);
    }
}

extern "C" void kernel_launch(void* const* d_in, const int* in_sizes, int n_in,
                              void* d_out, int out_size)
{
    const float* pred_cls      = (const float*)d_in[0];
    const float* pred_response = (const float*)d_in[1];
    const float* pred_bboxes   = (const float*)d_in[2];
    const float* tgt_box       = (const float*)d_in[3];
    const int*   tgt_idx_x     = (const int*)d_in[4];
    const int*   tgt_idx_y     = (const int*)d_in[5];
    const int*   tgt_idx_box   = (const int*)d_in[6];
    const int*   tgt_label     = (const int*)d_in[7];
    float* out = (float*)d_out;

    fused_kernel<<<GRID, 256>>>(pred_cls, pred_response, pred_bboxes,
                                tgt_box, tgt_idx_x, tgt_idx_y,
                                tgt_idx_box, tgt_label, out);
}